// round 10
// baseline (speedup 1.0000x reference)
#include <cuda_runtime.h>

#define HH 4096
#define WW 4096
#define NPIX (HH * WW)

// R9 structure (2D tiles, streaming hints, branchless FSEL body) + halo via
// warp shuffle: 6 scalar halo loads (24 L1 wavefronts/warp) -> 6 SHFL + 6
// predicated 1-wavefront edge loads.

__global__ void __launch_bounds__(256, 7) nms_kernel(
    const float* __restrict__ img,
    const float* __restrict__ theta,
    float* __restrict__ out)
{
    unsigned tid  = threadIdx.x;
    unsigned lane = tid & 31u;
    unsigned bx   = blockIdx.x & 15u;    // 16 tiles across (64 quads each)
    unsigned by   = blockIdx.x >> 4;     // 1024 tiles down (4 rows each)
    unsigned tx   = tid & 63u;           // warp = 32 consecutive tx in one row
    unsigned ty   = tid >> 6;

    unsigned h    = (by << 2) + ty;
    unsigned w0   = ((bx << 6) + tx) << 2;
    unsigned base = (h << 12) + w0;

    if (h == 0 || h == HH - 1) {
        __stcs(reinterpret_cast<float4*>(out + base), make_float4(0.f, 0.f, 0.f, 0.f));
        return;
    }

    const float* pc = img + base;

    // ---- 4 vector loads + predicated edge loads, all front-batched ----
    const float4 t4 = __ldcs(reinterpret_cast<const float4*>(theta + base));
    const float4 c4 = __ldg(reinterpret_cast<const float4*>(pc));
    const float4 u4 = __ldg(reinterpret_cast<const float4*>(pc - WW));
    const float4 d4 = __ldg(reinterpret_cast<const float4*>(pc + WW));

    // warp-edge halo loads (1 wavefront each; 2 active lanes per warp).
    // clamps only bind for border-zeroed outputs; clamped values never used.
    float e_lc = 0.f, e_lu = 0.f, e_ld = 0.f;   // lane 0: col w0-1, rows h-1,h,h+1
    float e_rc = 0.f, e_ru = 0.f, e_rd = 0.f;   // lane 31: col w0+4
    if (lane == 0) {
        int uli = (int)base - WW - 1; if (uli < 0) uli = 0;
        e_lc = __ldg(pc - 1);
        e_lu = __ldg(img + uli);
        e_ld = __ldg(pc + WW - 1);
    }
    if (lane == 31) {
        int dri = (int)base + WW + 4; if (dri >= NPIX) dri = NPIX - 1;
        e_rc = __ldg(pc + 4);
        e_ru = __ldg(pc - WW + 4);
        e_rd = __ldg(pc + WW + (dri - (int)base - WW));   // = img+dri
    }

    // ---- halo via shuffle (neighbor quad lives in adjacent lane) ----
    float lft = __shfl_up_sync(0xffffffffu, c4.w, 1);
    float ul  = __shfl_up_sync(0xffffffffu, u4.w, 1);
    float dl  = __shfl_up_sync(0xffffffffu, d4.w, 1);
    float rgt = __shfl_down_sync(0xffffffffu, c4.x, 1);
    float ur  = __shfl_down_sync(0xffffffffu, u4.x, 1);
    float dr  = __shfl_down_sync(0xffffffffu, d4.x, 1);
    if (lane == 0)  { lft = e_lc; ul = e_lu; dl = e_ld; }
    if (lane == 31) { rgt = e_rc; ur = e_ru; dr = e_rd; }

    const float RCP45 = 1.0f / 45.0f;   // RN(1/45)
    float o[4];

    // column layout (j = image column w0-1+j):
    // up:  ul  u4.x u4.y u4.z u4.w ur
    // ct:  lft c4.x c4.y c4.z c4.w rgt
    // dn:  dl  d4.x d4.y d4.z d4.w dr
    #define NMS_PX(i, UPL, UPC, UPR, CTL, CTC, CTR, DNL, DNC, DNR, TH)          \
    {                                                                            \
        float deg = __fmul_rn((TH), 57.29577951308232f);                         \
        if (deg < 0.f) deg = __fadd_rn(deg, 180.f);                              \
        float q0 = __fmul_rn(deg, RCP45);                                        \
        float rr = __fmaf_rn(-45.f, q0, deg);                                    \
        float qf = __fmaf_rn(rr, RCP45, q0);                                     \
        int   k  = __float2int_rn(qf);      /* F2I.RNI = half-even = jnp.round */\
        bool p0 = (k == 0) | (k == 4);      /* 0 / 180 deg  */                   \
        bool p1 = (k == 1);                 /* 45           */                   \
        bool p2 = (k == 2);                 /* 90           */                   \
        float a_dn = p1 ? (DNR) : (p2 ? (DNC) : (DNL));                          \
        float a    = p0 ? (CTR) : a_dn;                                          \
        float b_up = p1 ? (UPL) : (p2 ? (UPC) : (UPR));                          \
        float b    = p0 ? (CTL) : b_up;                                          \
        o[i] = ((CTC) >= fmaxf(a, b)) ? (CTC) : 0.f;                             \
    }

    NMS_PX(0, ul,   u4.x, u4.y,  lft,  c4.x, c4.y,  dl,   d4.x, d4.y, t4.x)
    NMS_PX(1, u4.x, u4.y, u4.z,  c4.x, c4.y, c4.z,  d4.x, d4.y, d4.z, t4.y)
    NMS_PX(2, u4.y, u4.z, u4.w,  c4.y, c4.z, c4.w,  d4.y, d4.z, d4.w, t4.z)
    NMS_PX(3, u4.z, u4.w, ur,    c4.z, c4.w, rgt,   d4.z, d4.w, dr,   t4.w)

    #undef NMS_PX

    // left / right image borders
    if (w0 == 0)       o[0] = 0.f;
    if (w0 == WW - 4)  o[3] = 0.f;

    __stcs(reinterpret_cast<float4*>(out + base),
           make_float4(o[0], o[1], o[2], o[3]));     // never re-read: stream it
}

extern "C" void kernel_launch(void* const* d_in, const int* in_sizes, int n_in,
                              void* d_out, int out_size)
{
    const float* img   = (const float*)d_in[0];
    const float* theta = (const float*)d_in[1];
    float*       out   = (float*)d_out;

    const int grid = 16 * 1024;   // 16 tiles-x * 1024 tiles-y
    nms_kernel<<<grid, 256>>>(img, theta, out);
}